// round 1
// baseline (speedup 1.0000x reference)
#include <cuda_runtime.h>
#include <cuda_bf16.h>
#include <math.h>

// ---------------- problem constants (from reference setup) ----------------
#define CC    16      // channels
#define TT    2000    // time samples
#define EE    256     // embedding
#define NFFT  200
#define HOPL  100
#define NF    101     // n_fft/2+1
#define NFR   19      // (T - NFFT)/HOP + 1
#define SEQ   (CC*NFR)   // 304
#define DEPTH 4
#define FF4   1024
#define HH    8
#define DH    32
#define BMAX  256
#define MMAX  (BMAX*SEQ)   // 77824

// ---------------- device scratch (no allocations allowed) ----------------
__device__ float g_H [ (size_t)MMAX*EE ];
__device__ float g_Y [ (size_t)MMAX*EE ];
__device__ float g_Q [ (size_t)MMAX*EE ];
__device__ float g_K [ (size_t)MMAX*EE ];
__device__ float g_V [ (size_t)MMAX*EE ];
__device__ float g_O [ (size_t)MMAX*EE ];
__device__ float g_FF[ (size_t)MMAX*FF4 ];
__device__ float g_CTX[ (size_t)BMAX*HH*DH*DH ];
__device__ float g_cosT[ NFFT*NF ];   // transposed: [n][k]
__device__ float g_sinT[ NFFT*NF ];
__device__ float g_win [ NFFT ];

// ---------------- table init (recomputed each launch; deterministic) ------
__global__ void init_tables_kernel() {
    int i = blockIdx.x * blockDim.x + threadIdx.x;
    if (i < NFFT*NF) {
        int n = i / NF, k = i % NF;
        int m = (k * n) % NFFT;             // exact angle reduction
        float a = (float)m / 100.0f;        // angle = pi * a
        g_cosT[i] = cospif(a);
        g_sinT[i] = sinpif(a);
    }
    if (i < NFFT) g_win[i] = 0.5f * (1.0f - cospif((float)i / 100.0f));
}

// ---------------- STFT (DFT) + |.| + freq projection + tokens + PE --------
// 8 frames per block. Output rows of g_H directly (seq index == linear frame id).
__global__ void __launch_bounds__(256) embed_kernel(
    const float* __restrict__ x, const int* __restrict__ noff_p,
    const float* __restrict__ projW, const float* __restrict__ projb,
    const float* __restrict__ chan_tok)
{
    __shared__ float frs[8][NFFT];
    __shared__ float mags[8][NF+3];
    int tid  = threadIdx.x;
    int base = blockIdx.x * 8;

    // load 8 frames (window folded in)
    for (int i = tid; i < 8*NFFT; i += 256) {
        int fl = i / NFFT, n = i % NFFT;
        int lid = base + fl;
        int b = lid / (CC*NFR); int rem = lid % (CC*NFR);
        int c = rem / NFR;      int f = rem % NFR;
        frs[fl][n] = x[((size_t)b*CC + c)*TT + f*HOPL + n] * g_win[n];
    }
    __syncthreads();

    // DFT: thread = frequency bin k, all 8 frames at once
    if (tid < NF) {
        float re[8] = {0,0,0,0,0,0,0,0}, im[8] = {0,0,0,0,0,0,0,0};
        for (int n = 0; n < NFFT; ++n) {
            float cv = g_cosT[n*NF + tid];
            float sv = g_sinT[n*NF + tid];
            #pragma unroll
            for (int fl = 0; fl < 8; ++fl) {
                float fv = frs[fl][n];
                re[fl] = fmaf(fv, cv, re[fl]);
                im[fl] = fmaf(fv, sv, im[fl]);
            }
        }
        #pragma unroll
        for (int fl = 0; fl < 8; ++fl)
            mags[fl][tid] = sqrtf(re[fl]*re[fl] + im[fl]*im[fl]);
    }
    __syncthreads();

    // projection: thread = output column e
    int e = tid;
    float acc[8] = {0,0,0,0,0,0,0,0};
    for (int f = 0; f < NF; ++f) {
        float w = projW[f*EE + e];
        #pragma unroll
        for (int fl = 0; fl < 8; ++fl) acc[fl] = fmaf(mags[fl][f], w, acc[fl]);
    }
    int noff  = *noff_p;
    float pb  = projb[e];
    int   j2  = e & ~1;
    float dv  = expf((float)j2 * (-9.210340371976184f / (float)EE)); // -ln(1e4)/E
    #pragma unroll
    for (int fl = 0; fl < 8; ++fl) {
        int lid = base + fl;
        int rem = lid % (CC*NFR);
        int c = rem / NFR; int f = rem % NFR;
        float arg = (float)f * dv;
        float pe  = (e & 1) ? cosf(arg) : sinf(arg);
        float ct  = chan_tok[(size_t)(noff + c)*EE + e];
        g_H[(size_t)lid*EE + e] = acc[fl] + pb + ct + pe;
    }
}

// ---------------- LayerNorm: one warp per row (E=256 -> 8 per lane) -------
__global__ void ln_kernel(const float* __restrict__ X, float* __restrict__ Y,
                          const float* __restrict__ g, const float* __restrict__ b,
                          int rows)
{
    int w    = (blockIdx.x * blockDim.x + threadIdx.x) >> 5;
    int lane = threadIdx.x & 31;
    if (w >= rows) return;
    const float* xr = X + (size_t)w*EE;
    float v[8]; float s = 0.f;
    #pragma unroll
    for (int i = 0; i < 8; ++i) { v[i] = xr[lane + 32*i]; s += v[i]; }
    #pragma unroll
    for (int o = 16; o; o >>= 1) s += __shfl_xor_sync(0xffffffffu, s, o);
    float mu = s * (1.f/256.f);
    float q = 0.f;
    #pragma unroll
    for (int i = 0; i < 8; ++i) { float d = v[i]-mu; q = fmaf(d,d,q); }
    #pragma unroll
    for (int o = 16; o; o >>= 1) q += __shfl_xor_sync(0xffffffffu, q, o);
    float r = rsqrtf(q * (1.f/256.f) + 1e-5f);
    float* yr = Y + (size_t)w*EE;
    #pragma unroll
    for (int i = 0; i < 8; ++i) {
        int c = lane + 32*i;
        yr[c] = (v[i]-mu)*r*g[c] + b[c];
    }
}

// ---------------- SGEMM 128x128x8, double-buffered, 8x8 per thread --------
// mode 0: C = A@B ; mode 1: C += A@B + bias ; mode 2: C = gelu(A@B + bias)
__device__ __forceinline__ float gelu_exact(float x) {
    return 0.5f * x * (1.0f + erff(x * 0.70710678118654752f));
}

__global__ void __launch_bounds__(256, 2) sgemm_kernel(
    const float* __restrict__ A, const float* __restrict__ B,
    float* __restrict__ C, const float* __restrict__ bias,
    int M, int N, int K, int mode)
{
    __shared__ float As[2][8][128];
    __shared__ float Bs[2][8][128];
    int tid = threadIdx.x;
    int bm = blockIdx.y, bn = blockIdx.x;
    const float* Ab = A + (size_t)bm*128*K;
    const float* Bb = B + (size_t)bn*128;
    int arow = tid >> 1, acol = (tid & 1) << 2;
    int brow = tid >> 5, bcol = (tid & 31) << 2;
    int tx = tid & 15, ty = tid >> 4;

    float acc[8][8];
    #pragma unroll
    for (int i = 0; i < 8; ++i)
        #pragma unroll
        for (int j = 0; j < 8; ++j) acc[i][j] = 0.f;

    {
        float4 a4 = *(const float4*)(Ab + (size_t)arow*K + acol);
        As[0][acol+0][arow]=a4.x; As[0][acol+1][arow]=a4.y;
        As[0][acol+2][arow]=a4.z; As[0][acol+3][arow]=a4.w;
        float4 b4 = *(const float4*)(Bb + (size_t)brow*N + bcol);
        *(float4*)&Bs[0][brow][bcol] = b4;
    }
    __syncthreads();

    int nt = K >> 3;
    int buf = 0;
    for (int t = 0; t < nt; ++t) {
        if (t + 1 < nt) {
            float4 a4 = *(const float4*)(Ab + (size_t)arow*K + ((t+1)<<3) + acol);
            float4 b4 = *(const float4*)(Bb + (size_t)(((t+1)<<3) + brow)*N + bcol);
            int nb = buf ^ 1;
            As[nb][acol+0][arow]=a4.x; As[nb][acol+1][arow]=a4.y;
            As[nb][acol+2][arow]=a4.z; As[nb][acol+3][arow]=a4.w;
            *(float4*)&Bs[nb][brow][bcol] = b4;
        }
        #pragma unroll
        for (int k = 0; k < 8; ++k) {
            float ar[8], br[8];
            *(float4*)&ar[0] = *(const float4*)&As[buf][k][ty*8];
            *(float4*)&ar[4] = *(const float4*)&As[buf][k][ty*8+4];
            *(float4*)&br[0] = *(const float4*)&Bs[buf][k][tx*8];
            *(float4*)&br[4] = *(const float4*)&Bs[buf][k][tx*8+4];
            #pragma unroll
            for (int i = 0; i < 8; ++i)
                #pragma unroll
                for (int j = 0; j < 8; ++j)
                    acc[i][j] = fmaf(ar[i], br[j], acc[i][j]);
        }
        __syncthreads();
        buf ^= 1;
    }

    float* Cb = C + (size_t)(bm*128 + ty*8)*N + bn*128 + tx*8;
    const float* bp = bias + (size_t)bn*128 + tx*8;   // only deref'd in mode 1/2
    #pragma unroll
    for (int i = 0; i < 8; ++i) {
        #pragma unroll
        for (int jj = 0; jj < 2; ++jj) {
            float4 v = make_float4(acc[i][jj*4+0], acc[i][jj*4+1],
                                   acc[i][jj*4+2], acc[i][jj*4+3]);
            if (mode == 1) {
                float4 o = *(float4*)(Cb + (size_t)i*N + jj*4);
                v.x += o.x + bp[jj*4+0]; v.y += o.y + bp[jj*4+1];
                v.z += o.z + bp[jj*4+2]; v.w += o.w + bp[jj*4+3];
            } else if (mode == 2) {
                v.x = gelu_exact(v.x + bp[jj*4+0]); v.y = gelu_exact(v.y + bp[jj*4+1]);
                v.z = gelu_exact(v.z + bp[jj*4+2]); v.w = gelu_exact(v.w + bp[jj*4+3]);
            }
            *(float4*)(Cb + (size_t)i*N + jj*4) = v;
        }
    }
}

// ---------------- fused k-softmax(seq) + ctx = k^T v  (per b,h) -----------
__global__ void __launch_bounds__(256) ctx_kernel(
    const float* __restrict__ K, const float* __restrict__ V,
    float* __restrict__ CTX)
{
    __shared__ float Ks[SEQ][DH+1];
    __shared__ float red[8][DH];
    __shared__ float colmax[DH], colinv[DH];
    int bh = blockIdx.x; int b = bh >> 3; int h = bh & 7;
    int tid = threadIdx.x;
    int d = tid & 31; int s = tid >> 5;
    const float* Kb = K + (size_t)b*SEQ*EE + h*DH;

    for (int i = tid; i < SEQ*DH; i += 256) {
        int n = i >> 5; int dd = i & 31;
        Ks[n][dd] = Kb[(size_t)n*EE + dd];
    }
    __syncthreads();

    float m = -1e30f;
    for (int n = s; n < SEQ; n += 8) m = fmaxf(m, Ks[n][d]);
    red[s][d] = m;
    __syncthreads();
    if (tid < 32) {
        float mm = red[0][d];
        #pragma unroll
        for (int i = 1; i < 8; ++i) mm = fmaxf(mm, red[i][d]);
        colmax[d] = mm;
    }
    __syncthreads();
    float cm = colmax[d];
    float sm = 0.f;
    for (int n = s; n < SEQ; n += 8) {
        float e = expf(Ks[n][d] - cm);
        Ks[n][d] = e; sm += e;
    }
    red[s][d] = sm;
    __syncthreads();
    if (tid < 32) {
        float ss = 0.f;
        #pragma unroll
        for (int i = 0; i < 8; ++i) ss += red[i][d];
        colinv[d] = 1.0f / ss;
    }
    __syncthreads();

    int e2 = tid & 31; int dbase = (tid >> 5) << 2;
    const float* Vb = V + (size_t)b*SEQ*EE + h*DH;
    float a0=0,a1=0,a2=0,a3=0;
    for (int n = 0; n < SEQ; ++n) {
        float vv = __ldg(&Vb[(size_t)n*EE + e2]);
        a0 = fmaf(Ks[n][dbase+0], vv, a0);
        a1 = fmaf(Ks[n][dbase+1], vv, a1);
        a2 = fmaf(Ks[n][dbase+2], vv, a2);
        a3 = fmaf(Ks[n][dbase+3], vv, a3);
    }
    float* Cb = CTX + (size_t)bh*DH*DH;
    Cb[(dbase+0)*DH + e2] = a0 * colinv[dbase+0];
    Cb[(dbase+1)*DH + e2] = a1 * colinv[dbase+1];
    Cb[(dbase+2)*DH + e2] = a2 * colinv[dbase+2];
    Cb[(dbase+3)*DH + e2] = a3 * colinv[dbase+3];
}

// ---------------- fused q-softmax(dh)*scale + o = q @ ctx (per b,h) -------
__global__ void __launch_bounds__(256) attnout_kernel(
    const float* __restrict__ Q, const float* __restrict__ CTX,
    float* __restrict__ O)
{
    __shared__ float ctxs[DH][DH];
    int bh = blockIdx.x; int b = bh >> 3; int h = bh & 7;
    int tid = threadIdx.x;
    for (int i = tid; i < DH*DH; i += 256)
        ctxs[i >> 5][i & 31] = CTX[(size_t)bh*DH*DH + i];
    __syncthreads();

    for (int n = tid; n < SEQ; n += 256) {
        const float* qr = Q + ((size_t)b*SEQ + n)*EE + h*DH;
        float qv[DH];
        #pragma unroll
        for (int i = 0; i < 8; ++i)
            *(float4*)&qv[i*4] = *(const float4*)&qr[i*4];
        float mx = qv[0];
        #pragma unroll
        for (int i = 1; i < 32; ++i) mx = fmaxf(mx, qv[i]);
        float sm = 0.f;
        #pragma unroll
        for (int i = 0; i < 32; ++i) { qv[i] = expf(qv[i]-mx); sm += qv[i]; }
        float inv = 0.17677669529663687f / sm;   // dh^-0.5 / sum
        float out[DH];
        #pragma unroll
        for (int j = 0; j < 32; ++j) out[j] = 0.f;
        #pragma unroll
        for (int d = 0; d < 32; ++d) {
            float qd = qv[d] * inv;
            #pragma unroll
            for (int j = 0; j < 32; ++j) out[j] = fmaf(qd, ctxs[d][j], out[j]);
        }
        float* orow = O + ((size_t)b*SEQ + n)*EE + h*DH;
        #pragma unroll
        for (int i = 0; i < 8; ++i)
            *(float4*)&orow[i*4] = *(float4*)&out[i*4];
    }
}

// ---------------- outputs ----------------
__global__ void mean_kernel(const float* __restrict__ H, float* __restrict__ out)
{
    int b = blockIdx.x, e = threadIdx.x;
    float s = 0.f;
    for (int n = 0; n < SEQ; ++n) s += H[((size_t)b*SEQ + n)*EE + e];
    out[(size_t)b*EE + e] = s * (1.0f/(float)SEQ);
}

__global__ void copy4_kernel(const float4* __restrict__ src, float4* __restrict__ dst,
                             size_t n4)
{
    size_t i = (size_t)blockIdx.x*256 + threadIdx.x;
    if (i < n4) dst[i] = src[i];
}

// ---------------- host ----------------
extern "C" void kernel_launch(void* const* d_in, const int* in_sizes, int n_in,
                              void* d_out, int out_size)
{
    const float* x     = (const float*)d_in[0];
    const int*   noff  = (const int*)  d_in[1];
    const float* projW = (const float*)d_in[2];
    const float* projb = (const float*)d_in[3];
    const float* chan  = (const float*)d_in[4];
    const float* Wq    = (const float*)d_in[5];
    const float* Wk    = (const float*)d_in[6];
    const float* Wv    = (const float*)d_in[7];
    const float* Wo    = (const float*)d_in[8];
    const float* bo    = (const float*)d_in[9];
    const float* ln1g  = (const float*)d_in[10];
    const float* ln1b  = (const float*)d_in[11];
    const float* ln2g  = (const float*)d_in[12];
    const float* ln2b  = (const float*)d_in[13];
    const float* W1    = (const float*)d_in[14];
    const float* b1    = (const float*)d_in[15];
    const float* W2    = (const float*)d_in[16];
    const float* b2    = (const float*)d_in[17];

    int Bn = in_sizes[0] / (CC*TT);
    int M  = Bn * SEQ;

    float *H, *Y, *Qb, *Kb, *Vb, *Ob, *FF, *CX;
    cudaGetSymbolAddress((void**)&H,  g_H);
    cudaGetSymbolAddress((void**)&Y,  g_Y);
    cudaGetSymbolAddress((void**)&Qb, g_Q);
    cudaGetSymbolAddress((void**)&Kb, g_K);
    cudaGetSymbolAddress((void**)&Vb, g_V);
    cudaGetSymbolAddress((void**)&Ob, g_O);
    cudaGetSymbolAddress((void**)&FF, g_FF);
    cudaGetSymbolAddress((void**)&CX, g_CTX);

    init_tables_kernel<<<(NFFT*NF + 255)/256, 256>>>();
    embed_kernel<<<M/8, 256>>>(x, noff, projW, projb, chan);

    dim3 gE (EE/128,  M/128);   // 256-wide GEMMs
    dim3 gF (FF4/128, M/128);   // 1024-wide GEMM
    int lnBlocks = (M + 7) / 8;

    for (int l = 0; l < DEPTH; ++l) {
        ln_kernel<<<lnBlocks, 256>>>(H, Y, ln1g + l*EE, ln1b + l*EE, M);
        sgemm_kernel<<<gE, 256>>>(Y, Wq + (size_t)l*EE*EE, Qb, nullptr, M, EE, EE, 0);
        sgemm_kernel<<<gE, 256>>>(Y, Wk + (size_t)l*EE*EE, Kb, nullptr, M, EE, EE, 0);
        sgemm_kernel<<<gE, 256>>>(Y, Wv + (size_t)l*EE*EE, Vb, nullptr, M, EE, EE, 0);
        ctx_kernel<<<Bn*HH, 256>>>(Kb, Vb, CX);
        attnout_kernel<<<Bn*HH, 256>>>(Qb, CX, Ob);
        sgemm_kernel<<<gE, 256>>>(Ob, Wo + (size_t)l*EE*EE, H, bo + (size_t)l*EE, M, EE, EE, 1);
        ln_kernel<<<lnBlocks, 256>>>(H, Y, ln2g + l*EE, ln2b + l*EE, M);
        sgemm_kernel<<<gF, 256>>>(Y, W1 + (size_t)l*EE*FF4, FF, b1 + (size_t)l*FF4, M, FF4, EE, 2);
        sgemm_kernel<<<gE, 256>>>(FF, W2 + (size_t)l*FF4*EE, H, b2 + (size_t)l*EE, M, EE, FF4, 1);
    }

    float* out = (float*)d_out;
    size_t meanN = (size_t)Bn * EE;
    size_t hN    = (size_t)M * EE;
    size_t outN  = (size_t)out_size;
    if (outN >= meanN + hN) {
        mean_kernel<<<Bn, EE>>>(H, out);
        copy4_kernel<<<(unsigned)((hN/4 + 255)/256), 256>>>(
            (const float4*)H, (float4*)(out + meanN), hN/4);
    } else if (outN >= hN) {
        copy4_kernel<<<(unsigned)((hN/4 + 255)/256), 256>>>(
            (const float4*)H, (float4*)out, hN/4);
    } else {
        mean_kernel<<<Bn, EE>>>(H, out);
    }
}

// round 3
// speedup vs baseline: 1.5260x; 1.5260x over previous
#include <cuda_runtime.h>
#include <cuda_bf16.h>
#include <math.h>
#include <stdint.h>

// ---------------- problem constants (from reference setup) ----------------
#define CC    16      // channels
#define TT    2000    // time samples
#define EE    256     // embedding
#define NFFT  200
#define HOPL  100
#define NF    101     // n_fft/2+1
#define NFR   19      // (T - NFFT)/HOP + 1
#define SEQ   (CC*NFR)   // 304
#define DEPTH 4
#define FF4   1024
#define HH    8
#define DH    32
#define BMAX  256
#define MMAX  (BMAX*SEQ)   // 77824

// ---------------- device scratch (no allocations allowed) ----------------
__device__ float g_H [ (size_t)MMAX*EE ];
__device__ float g_Y [ (size_t)MMAX*EE ];
__device__ float g_Q [ (size_t)MMAX*EE ];
__device__ float g_K [ (size_t)MMAX*EE ];
__device__ float g_V [ (size_t)MMAX*EE ];
__device__ float g_O [ (size_t)MMAX*EE ];
__device__ float g_FF[ (size_t)MMAX*FF4 ];
__device__ float g_CTX[ (size_t)BMAX*HH*DH*DH ];
__device__ float g_cosT[ NFFT*NF ];   // transposed: [n][k]
__device__ float g_sinT[ NFFT*NF ];
__device__ float g_win [ NFFT ];
// transposed weights per layer: Wq,Wk,Wv,Wo (4*65536) + W1t + W2t
#define LWT  (4*65536 + 262144 + 262144)   // 786432 floats per layer
__device__ float g_Wt[ (size_t)DEPTH * LWT ];

// ---------------- table init ------------------------------------------------
__global__ void init_tables_kernel() {
    int i = blockIdx.x * blockDim.x + threadIdx.x;
    if (i < NFFT*NF) {
        int n = i / NF, k = i % NF;
        int m = (k * n) % NFFT;
        float a = (float)m / 100.0f;
        g_cosT[i] = cospif(a);
        g_sinT[i] = sinpif(a);
    }
    if (i < NFFT) g_win[i] = 0.5f * (1.0f - cospif((float)i / 100.0f));
}

// ---------------- weight transpose: dst[n][k] = src[k][n] -------------------
__global__ void transpose_kernel(const float* __restrict__ s, float* __restrict__ d,
                                 int R, int C)
{
    __shared__ float t[32][33];
    int bx = blockIdx.x * 32, by = blockIdx.y * 32;
    int x = threadIdx.x, y = threadIdx.y;
    #pragma unroll
    for (int i = 0; i < 32; i += 8)
        t[y + i][x] = s[(size_t)(by + y + i) * C + bx + x];
    __syncthreads();
    #pragma unroll
    for (int i = 0; i < 32; i += 8)
        d[(size_t)(bx + y + i) * R + by + x] = t[x][y + i];
}

// ---------------- STFT (DFT) + |.| + freq projection + tokens + PE ----------
__global__ void __launch_bounds__(256) embed_kernel(
    const float* __restrict__ x, const int* __restrict__ noff_p,
    const float* __restrict__ projW, const float* __restrict__ projb,
    const float* __restrict__ chan_tok)
{
    __shared__ float frs[8][NFFT];
    __shared__ float mags[8][NF+3];
    int tid  = threadIdx.x;
    int base = blockIdx.x * 8;

    for (int i = tid; i < 8*NFFT; i += 256) {
        int fl = i / NFFT, n = i % NFFT;
        int lid = base + fl;
        int b = lid / (CC*NFR); int rem = lid % (CC*NFR);
        int c = rem / NFR;      int f = rem % NFR;
        frs[fl][n] = x[((size_t)b*CC + c)*TT + f*HOPL + n] * g_win[n];
    }
    __syncthreads();

    if (tid < NF) {
        float re[8] = {0,0,0,0,0,0,0,0}, im[8] = {0,0,0,0,0,0,0,0};
        for (int n = 0; n < NFFT; ++n) {
            float cv = g_cosT[n*NF + tid];
            float sv = g_sinT[n*NF + tid];
            #pragma unroll
            for (int fl = 0; fl < 8; ++fl) {
                float fv = frs[fl][n];
                re[fl] = fmaf(fv, cv, re[fl]);
                im[fl] = fmaf(fv, sv, im[fl]);
            }
        }
        #pragma unroll
        for (int fl = 0; fl < 8; ++fl)
            mags[fl][tid] = sqrtf(re[fl]*re[fl] + im[fl]*im[fl]);
    }
    __syncthreads();

    int e = tid;
    float acc[8] = {0,0,0,0,0,0,0,0};
    for (int f = 0; f < NF; ++f) {
        float w = projW[f*EE + e];
        #pragma unroll
        for (int fl = 0; fl < 8; ++fl) acc[fl] = fmaf(mags[fl][f], w, acc[fl]);
    }
    int noff  = *noff_p;
    float pb  = projb[e];
    int   j2  = e & ~1;
    float dv  = expf((float)j2 * (-9.210340371976184f / (float)EE));
    #pragma unroll
    for (int fl = 0; fl < 8; ++fl) {
        int lid = base + fl;
        int rem = lid % (CC*NFR);
        int c = rem / NFR; int f = rem % NFR;
        float arg = (float)f * dv;
        float pe  = (e & 1) ? cosf(arg) : sinf(arg);
        float ct  = chan_tok[(size_t)(noff + c)*EE + e];
        g_H[(size_t)lid*EE + e] = acc[fl] + pb + ct + pe;
    }
}

// ---------------- LayerNorm: one warp per row --------------------------------
__global__ void ln_kernel(const float* __restrict__ X, float* __restrict__ Y,
                          const float* __restrict__ g, const float* __restrict__ b,
                          int rows)
{
    int w    = (blockIdx.x * blockDim.x + threadIdx.x) >> 5;
    int lane = threadIdx.x & 31;
    if (w >= rows) return;
    const float* xr = X + (size_t)w*EE;
    float v[8]; float s = 0.f;
    #pragma unroll
    for (int i = 0; i < 8; ++i) { v[i] = xr[lane + 32*i]; s += v[i]; }
    #pragma unroll
    for (int o = 16; o; o >>= 1) s += __shfl_xor_sync(0xffffffffu, s, o);
    float mu = s * (1.f/256.f);
    float q = 0.f;
    #pragma unroll
    for (int i = 0; i < 8; ++i) { float d = v[i]-mu; q = fmaf(d,d,q); }
    #pragma unroll
    for (int o = 16; o; o >>= 1) q += __shfl_xor_sync(0xffffffffu, q, o);
    float r = rsqrtf(q * (1.f/256.f) + 1e-5f);
    float* yr = Y + (size_t)w*EE;
    #pragma unroll
    for (int i = 0; i < 8; ++i) {
        int c = lane + 32*i;
        yr[c] = (v[i]-mu)*r*g[c] + b[c];
    }
}

// =================== tf32 mma.sync GEMM ======================================
// C[M,N] = A[M,K] @ Bt[N,K]^T.  mode 0: C=AB ; 1: C+=AB+bias ; 2: C=gelu(AB+bias)
// CTA tile 128x128, 8 warps (2m x 4n), warp tile 64x32, K-chunk 32.
// Smem tile: 128 rows x 32 cols, row stride 40 floats, per-8-col permutation
// slot(c) = (c&3)*2 + ((c>>2)&1) so fragment pairs (k, k+4) are one lds.64.
#define TROW 40
#define TILE_F (128*TROW)          // 5120 floats per tile buffer
#define GEMM_SMEM_BYTES (4*TILE_F*4)   // A0,A1,B0,B1 = 81920 B

__device__ __forceinline__ float gelu_exact(float x) {
    return 0.5f * x * (1.0f + erff(x * 0.70710678118654752f));
}

__device__ __forceinline__ float f2tf32f(float x) {
    uint32_t u;
    asm("cvt.rna.tf32.f32 %0, %1;" : "=r"(u) : "f"(x));
    return __uint_as_float(u);
}

__device__ __forceinline__ void ldg_chunk(const float* __restrict__ G, int K,
                                          int t, float4* v, int tid)
{
    #pragma unroll
    for (int i = 0; i < 4; ++i) {
        int idx = tid + i*256;
        int row = idx >> 3, q = idx & 7;
        v[i] = *(const float4*)(G + (size_t)row*K + t*32 + q*4);
    }
}

__device__ __forceinline__ void sts_chunk(const float4* v, float* dst, int tid)
{
    #pragma unroll
    for (int i = 0; i < 4; ++i) {
        int idx = tid + i*256;
        int row = idx >> 3, q = idx & 7;
        float* p = dst + row*TROW + (q>>1)*8 + (q&1);
        p[0] = f2tf32f(v[i].x);
        p[2] = f2tf32f(v[i].y);
        p[4] = f2tf32f(v[i].z);
        p[6] = f2tf32f(v[i].w);
    }
}

__device__ __forceinline__ void mma_tf32(float* c, uint32_t a0, uint32_t a1,
                                         uint32_t a2, uint32_t a3,
                                         uint32_t b0, uint32_t b1)
{
    asm volatile(
        "mma.sync.aligned.m16n8k8.row.col.f32.tf32.tf32.f32 "
        "{%0,%1,%2,%3}, {%4,%5,%6,%7}, {%8,%9}, {%0,%1,%2,%3};"
        : "+f"(c[0]), "+f"(c[1]), "+f"(c[2]), "+f"(c[3])
        : "r"(a0), "r"(a1), "r"(a2), "r"(a3), "r"(b0), "r"(b1));
}

__global__ void __launch_bounds__(256) mma_gemm_kernel(
    const float* __restrict__ A, const float* __restrict__ Bt,
    float* __restrict__ C, const float* __restrict__ bias,
    int M, int N, int K, int mode)
{
    extern __shared__ float sm[];
    int tid = threadIdx.x, wid = tid >> 5, lane = tid & 31;
    int bm = blockIdx.y, bn = blockIdx.x;
    int wm = wid >> 2, wn = wid & 3;
    int g = lane >> 2, tg = lane & 3;

    const float* Ag = A  + (size_t)bm * 128 * K;
    const float* Bg = Bt + (size_t)bn * 128 * K;

    float acc[4][4][4];
    #pragma unroll
    for (int mt = 0; mt < 4; ++mt)
        #pragma unroll
        for (int nt = 0; nt < 4; ++nt)
            #pragma unroll
            for (int r = 0; r < 4; ++r) acc[mt][nt][r] = 0.f;

    float4 pa[4], pb[4];
    ldg_chunk(Ag, K, 0, pa, tid);
    ldg_chunk(Bg, K, 0, pb, tid);
    sts_chunk(pa, sm, tid);
    sts_chunk(pb, sm + 2*TILE_F, tid);
    __syncthreads();

    int nchunks = K >> 5;
    for (int t = 0; t < nchunks; ++t) {
        int buf = t & 1;
        if (t + 1 < nchunks) {
            ldg_chunk(Ag, K, t+1, pa, tid);
            ldg_chunk(Bg, K, t+1, pb, tid);
        }
        const float* As = sm + buf*TILE_F + (wm*64)*TROW;
        const float* Bs = sm + 2*TILE_F + buf*TILE_F + (wn*32)*TROW;
        #pragma unroll
        for (int kk = 0; kk < 4; ++kk) {
            uint32_t af[4][4], bf[4][2];
            #pragma unroll
            for (int mt = 0; mt < 4; ++mt) {
                float2 v0 = *(const float2*)(As + (mt*16 + g    )*TROW + kk*8 + 2*tg);
                float2 v1 = *(const float2*)(As + (mt*16 + g + 8)*TROW + kk*8 + 2*tg);
                af[mt][0] = __float_as_uint(v0.x); af[mt][2] = __float_as_uint(v0.y);
                af[mt][1] = __float_as_uint(v1.x); af[mt][3] = __float_as_uint(v1.y);
            }
            #pragma unroll
            for (int nt = 0; nt < 4; ++nt) {
                float2 v = *(const float2*)(Bs + (nt*8 + g)*TROW + kk*8 + 2*tg);
                bf[nt][0] = __float_as_uint(v.x); bf[nt][1] = __float_as_uint(v.y);
            }
            #pragma unroll
            for (int mt = 0; mt < 4; ++mt)
                #pragma unroll
                for (int nt = 0; nt < 4; ++nt)
                    mma_tf32(acc[mt][nt], af[mt][0], af[mt][1], af[mt][2], af[mt][3],
                             bf[nt][0], bf[nt][1]);
        }
        if (t + 1 < nchunks) {
            int nb = buf ^ 1;
            sts_chunk(pa, sm + nb*TILE_F, tid);
            sts_chunk(pb, sm + 2*TILE_F + nb*TILE_F, tid);
            __syncthreads();
        }
    }

    // epilogue
    size_t rowbase = (size_t)bm*128 + wm*64;
    int colbase = bn*128 + wn*32;
    #pragma unroll
    for (int mt = 0; mt < 4; ++mt) {
        #pragma unroll
        for (int nt = 0; nt < 4; ++nt) {
            size_t r0 = rowbase + mt*16 + g;
            int    c0 = colbase + nt*8 + 2*tg;
            float* p0 = C + r0*N + c0;
            float* p1 = C + (r0+8)*N + c0;
            float x0 = acc[mt][nt][0], y0 = acc[mt][nt][1];
            float x1 = acc[mt][nt][2], y1 = acc[mt][nt][3];
            if (mode == 1) {
                float2 o0 = *(float2*)p0, o1 = *(float2*)p1;
                float bx = bias[c0], by = bias[c0+1];
                x0 += o0.x + bx; y0 += o0.y + by;
                x1 += o1.x + bx; y1 += o1.y + by;
            } else if (mode == 2) {
                float bx = bias[c0], by = bias[c0+1];
                x0 = gelu_exact(x0 + bx); y0 = gelu_exact(y0 + by);
                x1 = gelu_exact(x1 + bx); y1 = gelu_exact(y1 + by);
            }
            *(float2*)p0 = make_float2(x0, y0);
            *(float2*)p1 = make_float2(x1, y1);
        }
    }
}

// ---------------- fused k-softmax(seq) + ctx = k^T v  (per b,h) --------------
__global__ void __launch_bounds__(256) ctx_kernel(
    const float* __restrict__ K, const float* __restrict__ V,
    float* __restrict__ CTX)
{
    __shared__ float Ks[SEQ][DH+1];
    __shared__ float red[8][DH];
    __shared__ float colmax[DH], colinv[DH];
    int bh = blockIdx.x; int b = bh >> 3; int h = bh & 7;
    int tid = threadIdx.x;
    int d = tid & 31; int s = tid >> 5;
    const float* Kb = K + (size_t)b*SEQ*EE + h*DH;

    for (int i = tid; i < SEQ*DH; i += 256) {
        int n = i >> 5; int dd = i & 31;
        Ks[n][dd] = Kb[(size_t)n*EE + dd];
    }
    __syncthreads();

    float m = -1e30f;
    for (int n = s; n < SEQ; n += 8) m = fmaxf(m, Ks[n][d]);
    red[s][d] = m;
    __syncthreads();
    if (tid < 32) {
        float mm = red[0][d];
        #pragma unroll
        for (int i = 1; i < 8; ++i) mm = fmaxf(mm, red[i][d]);
        colmax[d] = mm;
    }
    __syncthreads();
    float cm = colmax[d];
    float sm = 0.f;
    for (int n = s; n < SEQ; n += 8) {
        float e = expf(Ks[n][d] - cm);
        Ks[n][d] = e; sm += e;
    }
    red[s][d] = sm;
    __syncthreads();
    if (tid < 32) {
        float ss = 0.f;
        #pragma unroll
        for (int i = 0; i < 8; ++i) ss += red[i][d];
        colinv[d] = 1.0f / ss;
    }
    __syncthreads();

    int e2 = tid & 31; int dbase = (tid >> 5) << 2;
    const float* Vb = V + (size_t)b*SEQ*EE + h*DH;
    float a0=0,a1=0,a2=0,a3=0;
    for (int n = 0; n < SEQ; ++n) {
        float vv = __ldg(&Vb[(size_t)n*EE + e2]);
        a0 = fmaf(Ks[n][dbase+0], vv, a0);
        a1 = fmaf(Ks[n][dbase+1], vv, a1);
        a2 = fmaf(Ks[n][dbase+2], vv, a2);
        a3 = fmaf(Ks[n][dbase+3], vv, a3);
    }
    float* Cb = CTX + (size_t)bh*DH*DH;
    Cb[(dbase+0)*DH + e2] = a0 * colinv[dbase+0];
    Cb[(dbase+1)*DH + e2] = a1 * colinv[dbase+1];
    Cb[(dbase+2)*DH + e2] = a2 * colinv[dbase+2];
    Cb[(dbase+3)*DH + e2] = a3 * colinv[dbase+3];
}

// ---------------- fused q-softmax(dh)*scale + o = q @ ctx (per b,h) ----------
__global__ void __launch_bounds__(256) attnout_kernel(
    const float* __restrict__ Q, const float* __restrict__ CTX,
    float* __restrict__ O)
{
    __shared__ float ctxs[DH][DH];
    int bh = blockIdx.x; int b = bh >> 3; int h = bh & 7;
    int tid = threadIdx.x;
    for (int i = tid; i < DH*DH; i += 256)
        ctxs[i >> 5][i & 31] = CTX[(size_t)bh*DH*DH + i];
    __syncthreads();

    for (int n = tid; n < SEQ; n += 256) {
        const float* qr = Q + ((size_t)b*SEQ + n)*EE + h*DH;
        float qv[DH];
        #pragma unroll
        for (int i = 0; i < 8; ++i)
            *(float4*)&qv[i*4] = *(const float4*)&qr[i*4];
        float mx = qv[0];
        #pragma unroll
        for (int i = 1; i < 32; ++i) mx = fmaxf(mx, qv[i]);
        float sm = 0.f;
        #pragma unroll
        for (int i = 0; i < 32; ++i) { qv[i] = expf(qv[i]-mx); sm += qv[i]; }
        float inv = 0.17677669529663687f / sm;
        float out[DH];
        #pragma unroll
        for (int j = 0; j < 32; ++j) out[j] = 0.f;
        #pragma unroll
        for (int d = 0; d < 32; ++d) {
            float qd = qv[d] * inv;
            #pragma unroll
            for (int j = 0; j < 32; ++j) out[j] = fmaf(qd, ctxs[d][j], out[j]);
        }
        float* orow = O + ((size_t)b*SEQ + n)*EE + h*DH;
        #pragma unroll
        for (int i = 0; i < 8; ++i)
            *(float4*)&orow[i*4] = *(float4*)&out[i*4];
    }
}

// ---------------- outputs ----------------
__global__ void mean_kernel(const float* __restrict__ H, float* __restrict__ out)
{
    int b = blockIdx.x, e = threadIdx.x;
    float s = 0.f;
    for (int n = 0; n < SEQ; ++n) s += H[((size_t)b*SEQ + n)*EE + e];
    out[(size_t)b*EE + e] = s * (1.0f/(float)SEQ);
}

__global__ void copy4_kernel(const float4* __restrict__ src, float4* __restrict__ dst,
                             size_t n4)
{
    size_t i = (size_t)blockIdx.x*256 + threadIdx.x;
    if (i < n4) dst[i] = src[i];
}

// ---------------- host ----------------
extern "C" void kernel_launch(void* const* d_in, const int* in_sizes, int n_in,
                              void* d_out, int out_size)
{
    const float* x     = (const float*)d_in[0];
    const int*   noff  = (const int*)  d_in[1];
    const float* projW = (const float*)d_in[2];
    const float* projb = (const float*)d_in[3];
    const float* chan  = (const float*)d_in[4];
    const float* Wq    = (const float*)d_in[5];
    const float* Wk    = (const float*)d_in[6];
    const float* Wv    = (const float*)d_in[7];
    const float* Wo    = (const float*)d_in[8];
    const float* bo    = (const float*)d_in[9];
    const float* ln1g  = (const float*)d_in[10];
    const float* ln1b  = (const float*)d_in[11];
    const float* ln2g  = (const float*)d_in[12];
    const float* ln2b  = (const float*)d_in[13];
    const float* W1    = (const float*)d_in[14];
    const float* b1    = (const float*)d_in[15];
    const float* W2    = (const float*)d_in[16];
    const float* b2    = (const float*)d_in[17];

    int Bn = in_sizes[0] / (CC*TT);
    int M  = Bn * SEQ;

    float *H, *Y, *Qb, *Kb, *Vb, *Ob, *FF, *CX, *Wt;
    cudaGetSymbolAddress((void**)&H,  g_H);
    cudaGetSymbolAddress((void**)&Y,  g_Y);
    cudaGetSymbolAddress((void**)&Qb, g_Q);
    cudaGetSymbolAddress((void**)&Kb, g_K);
    cudaGetSymbolAddress((void**)&Vb, g_V);
    cudaGetSymbolAddress((void**)&Ob, g_O);
    cudaGetSymbolAddress((void**)&FF, g_FF);
    cudaGetSymbolAddress((void**)&CX, g_CTX);
    cudaGetSymbolAddress((void**)&Wt, g_Wt);

    cudaFuncSetAttribute(mma_gemm_kernel,
        cudaFuncAttributeMaxDynamicSharedMemorySize, GEMM_SMEM_BYTES);

    init_tables_kernel<<<(NFFT*NF + 255)/256, 256>>>();
    embed_kernel<<<M/8, 256>>>(x, noff, projW, projb, chan);

    // transpose weights -> K-contiguous rows
    dim3 tb(32, 8);
    for (int l = 0; l < DEPTH; ++l) {
        float* base = Wt + (size_t)l * LWT;
        transpose_kernel<<<dim3(8,8),  tb>>>(Wq + (size_t)l*65536,  base,          256, 256);
        transpose_kernel<<<dim3(8,8),  tb>>>(Wk + (size_t)l*65536,  base+65536,    256, 256);
        transpose_kernel<<<dim3(8,8),  tb>>>(Wv + (size_t)l*65536,  base+131072,   256, 256);
        transpose_kernel<<<dim3(8,8),  tb>>>(Wo + (size_t)l*65536,  base+196608,   256, 256);
        transpose_kernel<<<dim3(32,8), tb>>>(W1 + (size_t)l*262144, base+262144,   256, 1024);
        transpose_kernel<<<dim3(8,32), tb>>>(W2 + (size_t)l*262144, base+524288,  1024, 256);
    }

    dim3 gE (EE/128,  M/128);
    dim3 gF (FF4/128, M/128);
    int lnBlocks = (M + 7) / 8;

    for (int l = 0; l < DEPTH; ++l) {
        float* base = Wt + (size_t)l * LWT;
        ln_kernel<<<lnBlocks, 256>>>(H, Y, ln1g + l*EE, ln1b + l*EE, M);
        mma_gemm_kernel<<<gE, 256, GEMM_SMEM_BYTES>>>(Y, base,         Qb, nullptr, M, EE, EE, 0);
        mma_gemm_kernel<<<gE, 256, GEMM_SMEM_BYTES>>>(Y, base+65536,   Kb, nullptr, M, EE, EE, 0);
        mma_gemm_kernel<<<gE, 256, GEMM_SMEM_BYTES>>>(Y, base+131072,  Vb, nullptr, M, EE, EE, 0);
        ctx_kernel<<<Bn*HH, 256>>>(Kb, Vb, CX);
        attnout_kernel<<<Bn*HH, 256>>>(Qb, CX, Ob);
        mma_gemm_kernel<<<gE, 256, GEMM_SMEM_BYTES>>>(Ob, base+196608, H, bo + (size_t)l*EE, M, EE, EE, 1);
        ln_kernel<<<lnBlocks, 256>>>(H, Y, ln2g + l*EE, ln2b + l*EE, M);
        mma_gemm_kernel<<<gF, 256, GEMM_SMEM_BYTES>>>(Y,  base+262144, FF, b1 + (size_t)l*FF4, M, FF4, EE, 2);
        mma_gemm_kernel<<<gE, 256, GEMM_SMEM_BYTES>>>(FF, base+524288, H,  b2 + (size_t)l*EE,  M, EE, FF4, 1);
    }

    float* out = (float*)d_out;
    size_t meanN = (size_t)Bn * EE;
    size_t hN    = (size_t)M * EE;
    size_t outN  = (size_t)out_size;
    if (outN >= meanN + hN) {
        mean_kernel<<<Bn, EE>>>(H, out);
        copy4_kernel<<<(unsigned)((hN/4 + 255)/256), 256>>>(
            (const float4*)H, (float4*)(out + meanN), hN/4);
    } else if (outN >= hN) {
        copy4_kernel<<<(unsigned)((hN/4 + 255)/256), 256>>>(
            (const float4*)H, (float4*)out, hN/4);
    } else {
        mean_kernel<<<Bn, EE>>>(H, out);
    }
}

// round 4
// speedup vs baseline: 2.4256x; 1.5895x over previous
#include <cuda_runtime.h>
#include <cuda_bf16.h>
#include <math.h>
#include <stdint.h>

// ---------------- problem constants ----------------
#define CC    16
#define TT    2000
#define EE    256
#define NFFT  200
#define HOPL  100
#define NF    101
#define NFR   19
#define SEQ   (CC*NFR)   // 304
#define DEPTH 4
#define FF4   1024
#define HH    8
#define DH    32
#define BMAX  256
#define MMAX  (BMAX*SEQ)   // 77824
#define NQKV  768

// ---------------- device scratch ----------------
__device__ float          g_H  [ (size_t)MMAX*EE ];
__device__ __nv_bfloat16  g_Yb [ (size_t)MMAX*EE ];
__device__ __nv_bfloat16  g_QKV[ (size_t)MMAX*NQKV ];
__device__ __nv_bfloat16  g_Ob [ (size_t)MMAX*EE ];
__device__ __nv_bfloat16  g_FFb[ (size_t)MMAX*FF4 ];
__device__ float          g_CTX[ (size_t)BMAX*HH*DH*DH ];
__device__ float g_cosT[ NFFT*NF ];
__device__ float g_sinT[ NFFT*NF ];
__device__ float g_win [ NFFT ];
// transposed bf16 weights per layer: Wq,Wk,Wv (=QKV block 768x256), Wo, W1t, W2t
#define LWT  (4*65536 + 262144 + 262144)
__device__ __nv_bfloat16 g_Wt[ (size_t)DEPTH * LWT ];

__device__ __forceinline__ uint32_t smem_u32(const void* p) {
    uint32_t a;
    asm("{ .reg .u64 t; cvta.to.shared.u64 t, %1; cvt.u32.u64 %0, t; }" : "=r"(a) : "l"(p));
    return a;
}

// ---------------- table init ----------------
__global__ void init_tables_kernel() {
    int i = blockIdx.x * blockDim.x + threadIdx.x;
    if (i < NFFT*NF) {
        int n = i / NF, k = i % NF;
        int m = (k * n) % NFFT;
        float a = (float)m / 100.0f;
        g_cosT[i] = cospif(a);
        g_sinT[i] = sinpif(a);
    }
    if (i < NFFT) g_win[i] = 0.5f * (1.0f - cospif((float)i / 100.0f));
}

// ---------------- weight transpose -> bf16, dst[n][k] = src[k][n] ----------
__global__ void transpose_kernel(const float* __restrict__ s,
                                 __nv_bfloat16* __restrict__ d, int R, int C)
{
    __shared__ float t[32][33];
    int bx = blockIdx.x * 32, by = blockIdx.y * 32;
    int x = threadIdx.x, y = threadIdx.y;
    #pragma unroll
    for (int i = 0; i < 32; i += 8)
        t[y + i][x] = s[(size_t)(by + y + i) * C + bx + x];
    __syncthreads();
    #pragma unroll
    for (int i = 0; i < 32; i += 8)
        d[(size_t)(bx + y + i) * R + by + x] = __float2bfloat16_rn(t[x][y + i]);
}

// ---------------- STFT + |.| + projection + tokens + PE ----------
__global__ void __launch_bounds__(256) embed_kernel(
    const float* __restrict__ x, const int* __restrict__ noff_p,
    const float* __restrict__ projW, const float* __restrict__ projb,
    const float* __restrict__ chan_tok)
{
    __shared__ float frs[8][NFFT];
    __shared__ float mags[8][NF+3];
    int tid  = threadIdx.x;
    int base = blockIdx.x * 8;

    for (int i = tid; i < 8*NFFT; i += 256) {
        int fl = i / NFFT, n = i % NFFT;
        int lid = base + fl;
        int b = lid / (CC*NFR); int rem = lid % (CC*NFR);
        int c = rem / NFR;      int f = rem % NFR;
        frs[fl][n] = x[((size_t)b*CC + c)*TT + f*HOPL + n] * g_win[n];
    }
    __syncthreads();

    if (tid < NF) {
        float re[8] = {0,0,0,0,0,0,0,0}, im[8] = {0,0,0,0,0,0,0,0};
        for (int n = 0; n < NFFT; ++n) {
            float cv = g_cosT[n*NF + tid];
            float sv = g_sinT[n*NF + tid];
            #pragma unroll
            for (int fl = 0; fl < 8; ++fl) {
                float fv = frs[fl][n];
                re[fl] = fmaf(fv, cv, re[fl]);
                im[fl] = fmaf(fv, sv, im[fl]);
            }
        }
        #pragma unroll
        for (int fl = 0; fl < 8; ++fl)
            mags[fl][tid] = sqrtf(re[fl]*re[fl] + im[fl]*im[fl]);
    }
    __syncthreads();

    int e = tid;
    float acc[8] = {0,0,0,0,0,0,0,0};
    for (int f = 0; f < NF; ++f) {
        float w = projW[f*EE + e];
        #pragma unroll
        for (int fl = 0; fl < 8; ++fl) acc[fl] = fmaf(mags[fl][f], w, acc[fl]);
    }
    int noff  = *noff_p;
    float pb  = projb[e];
    int   j2  = e & ~1;
    float dv  = expf((float)j2 * (-9.210340371976184f / (float)EE));
    #pragma unroll
    for (int fl = 0; fl < 8; ++fl) {
        int lid = base + fl;
        int rem = lid % (CC*NFR);
        int c = rem / NFR; int f = rem % NFR;
        float arg = (float)f * dv;
        float pe  = (e & 1) ? cosf(arg) : sinf(arg);
        float ct  = chan_tok[(size_t)(noff + c)*EE + e];
        g_H[(size_t)lid*EE + e] = acc[fl] + pb + ct + pe;
    }
}

// ---------------- LayerNorm fp32 -> bf16, one warp per row ----------
__global__ void ln_kernel(const float* __restrict__ X, __nv_bfloat16* __restrict__ Y,
                          const float* __restrict__ g, const float* __restrict__ b,
                          int rows)
{
    int w    = (blockIdx.x * blockDim.x + threadIdx.x) >> 5;
    int lane = threadIdx.x & 31;
    if (w >= rows) return;
    const float* xr = X + (size_t)w*EE + lane*8;
    float v[8];
    *(float4*)&v[0] = *(const float4*)(xr);
    *(float4*)&v[4] = *(const float4*)(xr + 4);
    float s = 0.f;
    #pragma unroll
    for (int i = 0; i < 8; ++i) s += v[i];
    #pragma unroll
    for (int o = 16; o; o >>= 1) s += __shfl_xor_sync(0xffffffffu, s, o);
    float mu = s * (1.f/256.f);
    float q = 0.f;
    #pragma unroll
    for (int i = 0; i < 8; ++i) { float d = v[i]-mu; q = fmaf(d,d,q); }
    #pragma unroll
    for (int o = 16; o; o >>= 1) q += __shfl_xor_sync(0xffffffffu, q, o);
    float r = rsqrtf(q * (1.f/256.f) + 1e-5f);
    float gg[8], bb[8];
    *(float4*)&gg[0] = *(const float4*)(g + lane*8);
    *(float4*)&gg[4] = *(const float4*)(g + lane*8 + 4);
    *(float4*)&bb[0] = *(const float4*)(b + lane*8);
    *(float4*)&bb[4] = *(const float4*)(b + lane*8 + 4);
    __nv_bfloat162 o2[4];
    #pragma unroll
    for (int i = 0; i < 4; ++i) {
        float y0 = (v[2*i]  -mu)*r*gg[2*i]   + bb[2*i];
        float y1 = (v[2*i+1]-mu)*r*gg[2*i+1] + bb[2*i+1];
        o2[i] = __float22bfloat162_rn(make_float2(y0, y1));
    }
    *(uint4*)(Y + (size_t)w*EE + lane*8) = *(uint4*)o2;
}

// =================== bf16 mma.sync GEMM, cp.async 3-stage ====================
// C = A[M,K](bf16) @ Bt[N,K](bf16)^T
// mode 0: C(bf16) = AB ; mode 1: C(f32) += AB + bias ; mode 2: C(bf16) = gelu(AB+bias)
// CTA 128x128, 8 warps 2x4, warp 64x32, K-chunk 32.
// Smem rows: 32 bf16 (64B data) with 80B stride -> conflict-free ldmatrix.
#define ROWB    80
#define TILEB   (128*ROWB)       // 10240 B
#define STAGE_B (2*TILEB)        // A + B
#define GSMEM   (3*STAGE_B)      // 61440 B

__device__ __forceinline__ float gelu_exact(float x) {
    return 0.5f * x * (1.0f + erff(x * 0.70710678118654752f));
}

__device__ __forceinline__ void mma_bf16(float* c, uint32_t a0, uint32_t a1,
                                         uint32_t a2, uint32_t a3,
                                         uint32_t b0, uint32_t b1)
{
    asm volatile(
        "mma.sync.aligned.m16n8k16.row.col.f32.bf16.bf16.f32 "
        "{%0,%1,%2,%3}, {%4,%5,%6,%7}, {%8,%9}, {%0,%1,%2,%3};"
        : "+f"(c[0]), "+f"(c[1]), "+f"(c[2]), "+f"(c[3])
        : "r"(a0), "r"(a1), "r"(a2), "r"(a3), "r"(b0), "r"(b1));
}

__global__ void __launch_bounds__(256) mma_gemm_kernel(
    const __nv_bfloat16* __restrict__ A, const __nv_bfloat16* __restrict__ Bt,
    void* __restrict__ Cv, const float* __restrict__ bias,
    int M, int N, int K, int mode)
{
    extern __shared__ char smraw[];
    uint32_t sb = smem_u32(smraw);
    int tid = threadIdx.x, lane = tid & 31, wid = tid >> 5;
    int bm = blockIdx.y, bn = blockIdx.x;
    int wm = wid >> 2, wn = wid & 3;

    const __nv_bfloat16* Ag = A  + (size_t)bm * 128 * K;
    const __nv_bfloat16* Bg = Bt + (size_t)bn * 128 * K;

    float acc[4][4][4];
    #pragma unroll
    for (int mt = 0; mt < 4; ++mt)
        #pragma unroll
        for (int nt = 0; nt < 4; ++nt)
            #pragma unroll
            for (int r = 0; r < 4; ++r) acc[mt][nt][r] = 0.f;

    int row0 = tid >> 2, q0 = tid & 3;            // thread's copy slots
    int row1 = (tid + 256) >> 2, q1 = (tid + 256) & 3;

    auto copy_stage = [&](int t, int s) {
        uint32_t base = sb + s * STAGE_B;
        const __nv_bfloat16* sa0 = Ag + (size_t)row0 * K + t*32 + q0*8;
        const __nv_bfloat16* sb0 = Bg + (size_t)row0 * K + t*32 + q0*8;
        const __nv_bfloat16* sa1 = Ag + (size_t)row1 * K + t*32 + q1*8;
        const __nv_bfloat16* sb1 = Bg + (size_t)row1 * K + t*32 + q1*8;
        uint32_t dA0 = base + row0*ROWB + q0*16;
        uint32_t dB0 = base + TILEB + row0*ROWB + q0*16;
        uint32_t dA1 = base + row1*ROWB + q1*16;
        uint32_t dB1 = base + TILEB + row1*ROWB + q1*16;
        asm volatile("cp.async.cg.shared.global [%0], [%1], 16;" :: "r"(dA0), "l"(sa0) : "memory");
        asm volatile("cp.async.cg.shared.global [%0], [%1], 16;" :: "r"(dB0), "l"(sb0) : "memory");
        asm volatile("cp.async.cg.shared.global [%0], [%1], 16;" :: "r"(dA1), "l"(sa1) : "memory");
        asm volatile("cp.async.cg.shared.global [%0], [%1], 16;" :: "r"(dB1), "l"(sb1) : "memory");
    };

    int nc = K >> 5;
    copy_stage(0, 0);
    asm volatile("cp.async.commit_group;" ::: "memory");
    copy_stage(1, 1);
    asm volatile("cp.async.commit_group;" ::: "memory");

    for (int t = 0; t < nc; ++t) {
        asm volatile("cp.async.wait_group 1;" ::: "memory");
        __syncthreads();
        if (t + 2 < nc) copy_stage(t + 2, (t + 2) % 3);
        asm volatile("cp.async.commit_group;" ::: "memory");

        int s = t % 3;
        uint32_t Abase = sb + s*STAGE_B + (wm*64)*ROWB;
        uint32_t Bbase = sb + s*STAGE_B + TILEB + (wn*32)*ROWB;
        #pragma unroll
        for (int kk = 0; kk < 2; ++kk) {
            uint32_t af[4][4], bfr[2][4];
            #pragma unroll
            for (int mt = 0; mt < 4; ++mt) {
                uint32_t ad = Abase + (uint32_t)(mt*16 + (lane & 15))*ROWB
                            + (uint32_t)(lane >> 4)*16 + kk*32;
                asm volatile("ldmatrix.sync.aligned.m8n8.x4.shared.b16 {%0,%1,%2,%3}, [%4];"
                    : "=r"(af[mt][0]), "=r"(af[mt][1]), "=r"(af[mt][2]), "=r"(af[mt][3])
                    : "r"(ad));
            }
            #pragma unroll
            for (int ng = 0; ng < 2; ++ng) {
                uint32_t bd = Bbase + (uint32_t)(ng*16 + (lane & 7) + ((lane >> 4) & 1)*8)*ROWB
                            + (uint32_t)((lane >> 3) & 1)*16 + kk*32;
                asm volatile("ldmatrix.sync.aligned.m8n8.x4.shared.b16 {%0,%1,%2,%3}, [%4];"
                    : "=r"(bfr[ng][0]), "=r"(bfr[ng][1]), "=r"(bfr[ng][2]), "=r"(bfr[ng][3])
                    : "r"(bd));
            }
            #pragma unroll
            for (int mt = 0; mt < 4; ++mt)
                #pragma unroll
                for (int nt = 0; nt < 4; ++nt) {
                    uint32_t b0 = bfr[nt >> 1][(nt & 1)*2 + 0];
                    uint32_t b1 = bfr[nt >> 1][(nt & 1)*2 + 1];
                    mma_bf16(acc[mt][nt], af[mt][0], af[mt][1], af[mt][2], af[mt][3], b0, b1);
                }
        }
    }

    // epilogue: lane holds (row g, cols 2t,2t+1) and (row g+8, same cols)
    int g = lane >> 2, t4 = lane & 3;
    size_t rowbase = (size_t)bm*128 + wm*64;
    int colbase = bn*128 + wn*32;
    #pragma unroll
    for (int mt = 0; mt < 4; ++mt) {
        #pragma unroll
        for (int nt = 0; nt < 4; ++nt) {
            size_t r0 = rowbase + mt*16 + g;
            int    c0 = colbase + nt*8 + 2*t4;
            float x0 = acc[mt][nt][0], y0 = acc[mt][nt][1];
            float x1 = acc[mt][nt][2], y1 = acc[mt][nt][3];
            if (mode == 0) {
                __nv_bfloat16* Cb = (__nv_bfloat16*)Cv;
                *(__nv_bfloat162*)(Cb + r0*N + c0)     = __float22bfloat162_rn(make_float2(x0, y0));
                *(__nv_bfloat162*)(Cb + (r0+8)*N + c0) = __float22bfloat162_rn(make_float2(x1, y1));
            } else if (mode == 1) {
                float* Cf = (float*)Cv;
                float bx = bias[c0], by = bias[c0+1];
                float2 o0 = *(float2*)(Cf + r0*N + c0);
                float2 o1 = *(float2*)(Cf + (r0+8)*N + c0);
                *(float2*)(Cf + r0*N + c0)     = make_float2(x0 + o0.x + bx, y0 + o0.y + by);
                *(float2*)(Cf + (r0+8)*N + c0) = make_float2(x1 + o1.x + bx, y1 + o1.y + by);
            } else {
                __nv_bfloat16* Cb = (__nv_bfloat16*)Cv;
                float bx = bias[c0], by = bias[c0+1];
                *(__nv_bfloat162*)(Cb + r0*N + c0) =
                    __float22bfloat162_rn(make_float2(gelu_exact(x0+bx), gelu_exact(y0+by)));
                *(__nv_bfloat162*)(Cb + (r0+8)*N + c0) =
                    __float22bfloat162_rn(make_float2(gelu_exact(x1+bx), gelu_exact(y1+by)));
            }
        }
    }
}

// ---------------- fused k-softmax(seq) + ctx = k^T v (per b,h) ----------
__global__ void __launch_bounds__(256) ctx_kernel(
    const __nv_bfloat16* __restrict__ QKV, float* __restrict__ CTX)
{
    __shared__ float Ks[SEQ][DH+1];
    __shared__ float red[8][DH];
    __shared__ float colmax[DH], colinv[DH];
    int bh = blockIdx.x; int b = bh >> 3; int h = bh & 7;
    int tid = threadIdx.x;
    int d = tid & 31; int s = tid >> 5;
    const __nv_bfloat16* Kb = QKV + (size_t)b*SEQ*NQKV + 256 + h*DH;

    for (int i = tid; i < SEQ*DH; i += 256) {
        int n = i >> 5; int dd = i & 31;
        Ks[n][dd] = __bfloat162float(Kb[(size_t)n*NQKV + dd]);
    }
    __syncthreads();

    float m = -1e30f;
    for (int n = s; n < SEQ; n += 8) m = fmaxf(m, Ks[n][d]);
    red[s][d] = m;
    __syncthreads();
    if (tid < 32) {
        float mm = red[0][d];
        #pragma unroll
        for (int i = 1; i < 8; ++i) mm = fmaxf(mm, red[i][d]);
        colmax[d] = mm;
    }
    __syncthreads();
    float cm = colmax[d];
    float sm = 0.f;
    for (int n = s; n < SEQ; n += 8) {
        float e = expf(Ks[n][d] - cm);
        Ks[n][d] = e; sm += e;
    }
    red[s][d] = sm;
    __syncthreads();
    if (tid < 32) {
        float ss = 0.f;
        #pragma unroll
        for (int i = 0; i < 8; ++i) ss += red[i][d];
        colinv[d] = 1.0f / ss;
    }
    __syncthreads();

    int e2 = tid & 31; int dbase = (tid >> 5) << 2;
    const __nv_bfloat16* Vb = QKV + (size_t)b*SEQ*NQKV + 512 + h*DH;
    float a0=0,a1=0,a2=0,a3=0;
    for (int n = 0; n < SEQ; ++n) {
        float vv = __bfloat162float(Vb[(size_t)n*NQKV + e2]);
        a0 = fmaf(Ks[n][dbase+0], vv, a0);
        a1 = fmaf(Ks[n][dbase+1], vv, a1);
        a2 = fmaf(Ks[n][dbase+2], vv, a2);
        a3 = fmaf(Ks[n][dbase+3], vv, a3);
    }
    float* Cb = CTX + (size_t)bh*DH*DH;
    Cb[(dbase+0)*DH + e2] = a0 * colinv[dbase+0];
    Cb[(dbase+1)*DH + e2] = a1 * colinv[dbase+1];
    Cb[(dbase+2)*DH + e2] = a2 * colinv[dbase+2];
    Cb[(dbase+3)*DH + e2] = a3 * colinv[dbase+3];
}

// ---------------- fused q-softmax(dh)*scale + o = q @ ctx (per b,h) ----------
__global__ void __launch_bounds__(256) attnout_kernel(
    const __nv_bfloat16* __restrict__ QKV, const float* __restrict__ CTX,
    __nv_bfloat16* __restrict__ O)
{
    __shared__ float ctxs[DH][DH];
    int bh = blockIdx.x; int b = bh >> 3; int h = bh & 7;
    int tid = threadIdx.x;
    for (int i = tid; i < DH*DH; i += 256)
        ctxs[i >> 5][i & 31] = CTX[(size_t)bh*DH*DH + i];
    __syncthreads();

    for (int n = tid; n < SEQ; n += 256) {
        const __nv_bfloat16* qr = QKV + ((size_t)b*SEQ + n)*NQKV + h*DH;
        float qv[DH];
        const uint4* q4 = (const uint4*)qr;
        #pragma unroll
        for (int i = 0; i < 4; ++i) {
            uint4 u = q4[i];
            uint32_t w[4] = {u.x, u.y, u.z, u.w};
            #pragma unroll
            for (int j = 0; j < 4; ++j) {
                float2 p = __bfloat1622float2(*reinterpret_cast<__nv_bfloat162*>(&w[j]));
                qv[i*8 + j*2]     = p.x;
                qv[i*8 + j*2 + 1] = p.y;
            }
        }
        float mx = qv[0];
        #pragma unroll
        for (int i = 1; i < 32; ++i) mx = fmaxf(mx, qv[i]);
        float sm = 0.f;
        #pragma unroll
        for (int i = 0; i < 32; ++i) { qv[i] = expf(qv[i]-mx); sm += qv[i]; }
        float inv = 0.17677669529663687f / sm;
        float out[DH];
        #pragma unroll
        for (int j = 0; j < 32; ++j) out[j] = 0.f;
        #pragma unroll
        for (int d = 0; d < 32; ++d) {
            float qd = qv[d] * inv;
            #pragma unroll
            for (int j = 0; j < 32; ++j) out[j] = fmaf(qd, ctxs[d][j], out[j]);
        }
        __nv_bfloat16* orow = O + ((size_t)b*SEQ + n)*EE + h*DH;
        #pragma unroll
        for (int i = 0; i < 4; ++i) {
            __nv_bfloat162 o2[4];
            #pragma unroll
            for (int j = 0; j < 4; ++j)
                o2[j] = __float22bfloat162_rn(make_float2(out[i*8+j*2], out[i*8+j*2+1]));
            *(uint4*)(orow + i*8) = *(uint4*)o2;
        }
    }
}

// ---------------- outputs ----------------
__global__ void mean_kernel(const float* __restrict__ H, float* __restrict__ out)
{
    int b = blockIdx.x, e = threadIdx.x;
    float s = 0.f;
    for (int n = 0; n < SEQ; ++n) s += H[((size_t)b*SEQ + n)*EE + e];
    out[(size_t)b*EE + e] = s * (1.0f/(float)SEQ);
}

__global__ void copy4_kernel(const float4* __restrict__ src, float4* __restrict__ dst,
                             size_t n4)
{
    size_t i = (size_t)blockIdx.x*256 + threadIdx.x;
    if (i < n4) dst[i] = src[i];
}

// ---------------- host ----------------
extern "C" void kernel_launch(void* const* d_in, const int* in_sizes, int n_in,
                              void* d_out, int out_size)
{
    const float* x     = (const float*)d_in[0];
    const int*   noff  = (const int*)  d_in[1];
    const float* projW = (const float*)d_in[2];
    const float* projb = (const float*)d_in[3];
    const float* chan  = (const float*)d_in[4];
    const float* Wq    = (const float*)d_in[5];
    const float* Wk    = (const float*)d_in[6];
    const float* Wv    = (const float*)d_in[7];
    const float* Wo    = (const float*)d_in[8];
    const float* bo    = (const float*)d_in[9];
    const float* ln1g  = (const float*)d_in[10];
    const float* ln1b  = (const float*)d_in[11];
    const float* ln2g  = (const float*)d_in[12];
    const float* ln2b  = (const float*)d_in[13];
    const float* W1    = (const float*)d_in[14];
    const float* b1    = (const float*)d_in[15];
    const float* W2    = (const float*)d_in[16];
    const float* b2    = (const float*)d_in[17];

    int Bn = in_sizes[0] / (CC*TT);
    int M  = Bn * SEQ;

    float *H, *CX;
    __nv_bfloat16 *Yb, *QKV, *Ob, *FFb, *Wt;
    cudaGetSymbolAddress((void**)&H,   g_H);
    cudaGetSymbolAddress((void**)&Yb,  g_Yb);
    cudaGetSymbolAddress((void**)&QKV, g_QKV);
    cudaGetSymbolAddress((void**)&Ob,  g_Ob);
    cudaGetSymbolAddress((void**)&FFb, g_FFb);
    cudaGetSymbolAddress((void**)&CX,  g_CTX);
    cudaGetSymbolAddress((void**)&Wt,  g_Wt);

    cudaFuncSetAttribute(mma_gemm_kernel,
        cudaFuncAttributeMaxDynamicSharedMemorySize, GSMEM);

    init_tables_kernel<<<(NFFT*NF + 255)/256, 256>>>();
    embed_kernel<<<M/8, 256>>>(x, noff, projW, projb, chan);

    dim3 tb(32, 8);
    for (int l = 0; l < DEPTH; ++l) {
        __nv_bfloat16* base = Wt + (size_t)l * LWT;
        transpose_kernel<<<dim3(8,8),  tb>>>(Wq + (size_t)l*65536,  base,          256, 256);
        transpose_kernel<<<dim3(8,8),  tb>>>(Wk + (size_t)l*65536,  base+65536,    256, 256);
        transpose_kernel<<<dim3(8,8),  tb>>>(Wv + (size_t)l*65536,  base+131072,   256, 256);
        transpose_kernel<<<dim3(8,8),  tb>>>(Wo + (size_t)l*65536,  base+196608,   256, 256);
        transpose_kernel<<<dim3(32,8), tb>>>(W1 + (size_t)l*262144, base+262144,   256, 1024);
        transpose_kernel<<<dim3(8,32), tb>>>(W2 + (size_t)l*262144, base+524288,  1024, 256);
    }

    dim3 gQKV(NQKV/128, M/128);
    dim3 gE  (EE/128,   M/128);
    dim3 gF  (FF4/128,  M/128);
    int lnBlocks = (M + 7) / 8;

    for (int l = 0; l < DEPTH; ++l) {
        __nv_bfloat16* base = Wt + (size_t)l * LWT;
        ln_kernel<<<lnBlocks, 256>>>(H, Yb, ln1g + l*EE, ln1b + l*EE, M);
        mma_gemm_kernel<<<gQKV, 256, GSMEM>>>(Yb, base, QKV, nullptr, M, NQKV, EE, 0);
        ctx_kernel<<<Bn*HH, 256>>>(QKV, CX);
        attnout_kernel<<<Bn*HH, 256>>>(QKV, CX, Ob);
        mma_gemm_kernel<<<gE, 256, GSMEM>>>(Ob, base+196608, H, bo + (size_t)l*EE, M, EE, EE, 1);
        ln_kernel<<<lnBlocks, 256>>>(H, Yb, ln2g + l*EE, ln2b + l*EE, M);
        mma_gemm_kernel<<<gF, 256, GSMEM>>>(Yb,  base+262144, FFb, b1 + (size_t)l*FF4, M, FF4, EE, 2);
        mma_gemm_kernel<<<gE, 256, GSMEM>>>(FFb, base+524288, H,   b2 + (size_t)l*EE,  M, EE, FF4, 1);
    }

    float* out = (float*)d_out;
    size_t meanN = (size_t)Bn * EE;
    size_t hN    = (size_t)M * EE;
    size_t outN  = (size_t)out_size;
    if (outN >= meanN + hN) {
        mean_kernel<<<Bn, EE>>>(H, out);
        copy4_kernel<<<(unsigned)((hN/4 + 255)/256), 256>>>(
            (const float4*)H, (float4*)(out + meanN), hN/4);
    } else if (outN >= hN) {
        copy4_kernel<<<(unsigned)((hN/4 + 255)/256), 256>>>(
            (const float4*)H, (float4*)out, hN/4);
    } else {
        mean_kernel<<<Bn, EE>>>(H, out);
    }
}